// round 1
// baseline (speedup 1.0000x reference)
#include <cuda_runtime.h>
#include <math.h>

#define HH    512
#define NPIX  (HH*HH)
#define FD    128
#define NR    363
#define BM    64
#define GEMM_THREADS 256
#define TILES_PER_TYPE ((NPIX + BM - 1) / BM)   // 4096

// ---------------- device scratch (no allocations allowed) ----------------
__device__ float g_sum_re[NR*FD];
__device__ float g_sum_im[NR*FD];
__device__ float g_mean_re[NR*FD];
__device__ float g_mean_im[NR*FD];
__device__ int   g_rcount[NR];
__device__ int   g_cnt[2];
__device__ int   g_list[2][NPIX];

// exact integer ring id: floor(sqrt((i-256)^2 + (j-256)^2)), matches float64 floor(sqrt)
__device__ __forceinline__ int ring_of(int p) {
    int i = (p >> 9) - 256;
    int j = (p & 511) - 256;
    int q = i*i + j*j;
    int s = __float2int_rd(sqrtf((float)q));
    while (s*s > q) --s;
    while ((s+1)*(s+1) <= q) ++s;
    return s;
}

// ---------------- kernel 0: zero accumulators ----------------
__global__ void k_zero() {
    int t = blockIdx.x * blockDim.x + threadIdx.x;
    if (t < NR*FD) { g_sum_re[t] = 0.f; g_sum_im[t] = 0.f; }
    if (t < NR)    g_rcount[t] = 0;
    if (t < 2)     g_cnt[t] = 0;
}

// ---------------- kernel 1: ring reduce inputs + partition pixels ----------------
// one warp per pixel
__global__ void k_accum(const float* __restrict__ img_re,
                        const float* __restrict__ img_im,
                        const int*   __restrict__ mask) {
    int gw   = (blockIdx.x * blockDim.x + threadIdx.x) >> 5;
    int lane = threadIdx.x & 31;
    if (gw >= NPIX) return;
    int p    = gw;
    int ring = ring_of(p);
    int m    = mask[p];
    if (lane == 0) {
        atomicAdd(&g_rcount[ring], 1);
        int pos = atomicAdd(&g_cnt[m], 1);
        g_list[m][pos] = p;
    }
    if (m == 0) {
        float4 a = ((const float4*)(img_re + (size_t)p * FD))[lane];
        float4 b = ((const float4*)(img_im + (size_t)p * FD))[lane];
        float* dr = &g_sum_re[ring*FD + lane*4];
        float* di = &g_sum_im[ring*FD + lane*4];
        asm volatile("red.global.add.v4.f32 [%0], {%1,%2,%3,%4};"
                     :: "l"(dr), "f"(a.x), "f"(a.y), "f"(a.z), "f"(a.w) : "memory");
        asm volatile("red.global.add.v4.f32 [%0], {%1,%2,%3,%4};"
                     :: "l"(di), "f"(b.x), "f"(b.y), "f"(b.z), "f"(b.w) : "memory");
    }
}

// ---------------- kernel 2: ring sums @ W1 (complex) / count -> ring means ----------------
__global__ void k_ringmm(const float* __restrict__ w1re,
                         const float* __restrict__ w1im) {
    __shared__ float sre[FD], sim[FD];
    int r = blockIdx.x, f = threadIdx.x;
    sre[f] = g_sum_re[r*FD + f];
    sim[f] = g_sum_im[r*FD + f];
    __syncthreads();
    float accr = 0.f, acci = 0.f;
    #pragma unroll 4
    for (int k = 0; k < FD; k++) {
        float wr = w1re[k*FD + f];
        float wi = w1im[k*FD + f];
        accr += sre[k]*wr - sim[k]*wi;
        acci += sre[k]*wi + sim[k]*wr;
    }
    float c = (float)max(g_rcount[r], 1);
    g_mean_re[r*FD + f] = accr / c;
    g_mean_im[r*FD + f] = acci / c;
}

// ---------------- kernel 3: main gather complex-GEMM + fused epilogue ----------------
// blocks [0, 4096): mask==0 pixels with W1, epilogue 0.5*(y+s)
// blocks [4096, 8192): mask==1 pixels with W2, epilogue y - s
__global__ __launch_bounds__(GEMM_THREADS)
void k_gemm(const float* __restrict__ img_re, const float* __restrict__ img_im,
            const float* __restrict__ w1re, const float* __restrict__ w1im,
            const float* __restrict__ w2re, const float* __restrict__ w2im,
            float* __restrict__ out) {
    extern __shared__ float smbuf[];
    float* As_re = smbuf;                 // BM x 132 (padded)
    float* As_im = As_re + BM*132;
    float* Bs_re = As_im + BM*132;        // 128 x 128
    float* Bs_im = Bs_re + FD*FD;
    int*   s_p    = (int*)(Bs_im + FD*FD); // BM
    int*   s_ring = s_p + BM;              // BM

    int bid  = blockIdx.x;
    int type = (bid >= TILES_PER_TYPE) ? 1 : 0;
    int tile = type ? bid - TILES_PER_TYPE : bid;
    int cnt  = g_cnt[type];
    int m_base = tile * BM;
    if (m_base >= cnt) return;

    int t = threadIdx.x;
    const float* wre = type ? w2re : w1re;
    const float* wim = type ? w2im : w1im;

    // load B (full 128x128 re+im), coalesced float4
    #pragma unroll
    for (int c = 0; c < 16; c++) {
        int off = c*1024 + t*4;
        *(float4*)&Bs_re[off] = *(const float4*)&wre[off];
        *(float4*)&Bs_im[off] = *(const float4*)&wim[off];
    }

    // load A: 4 threads per row, gathered via index list
    {
        int row = t >> 2, tq = t & 3;
        int grow = m_base + row;
        int p = -1, rg = 0;
        if (grow < cnt) { p = g_list[type][grow]; rg = ring_of(p); }
        if (tq == 0) { s_p[row] = p; s_ring[row] = rg; }
        if (p >= 0) {
            const float4* ar4 = (const float4*)(img_re + (size_t)p * FD);
            const float4* ai4 = (const float4*)(img_im + (size_t)p * FD);
            #pragma unroll
            for (int c = 0; c < 8; c++) {
                int c4 = c*4 + tq;
                *(float4*)&As_re[row*132 + c4*4] = ar4[c4];
                *(float4*)&As_im[row*132 + c4*4] = ai4[c4];
            }
        } else {
            float4 z = make_float4(0.f, 0.f, 0.f, 0.f);
            #pragma unroll
            for (int c = 0; c < 8; c++) {
                int c4 = c*4 + tq;
                *(float4*)&As_re[row*132 + c4*4] = z;
                *(float4*)&As_im[row*132 + c4*4] = z;
            }
        }
    }
    __syncthreads();

    // microkernel: 8 pixels x 4 features, complex
    int nq = t & 31, mq = t >> 5;
    float accr[8][4], acci[8][4];
    #pragma unroll
    for (int i = 0; i < 8; i++)
        #pragma unroll
        for (int j = 0; j < 4; j++) { accr[i][j] = 0.f; acci[i][j] = 0.f; }

    const float* Ar = As_re + (mq*8)*132;
    const float* Ai = As_im + (mq*8)*132;
    const float* Br = Bs_re + nq*4;
    const float* Bi = Bs_im + nq*4;

    #pragma unroll 4
    for (int k = 0; k < FD; k++) {
        float ar[8], ai[8];
        #pragma unroll
        for (int i = 0; i < 8; i++) { ar[i] = Ar[i*132 + k]; ai[i] = Ai[i*132 + k]; }
        float4 br4 = *(const float4*)&Br[k*FD];
        float4 bi4 = *(const float4*)&Bi[k*FD];
        float brv[4] = {br4.x, br4.y, br4.z, br4.w};
        float biv[4] = {bi4.x, bi4.y, bi4.z, bi4.w};
        #pragma unroll
        for (int i = 0; i < 8; i++)
            #pragma unroll
            for (int j = 0; j < 4; j++) {
                accr[i][j] += ar[i]*brv[j] - ai[i]*biv[j];
                acci[i][j] += ar[i]*biv[j] + ai[i]*brv[j];
            }
    }

    // fused epilogue: combine with ring mean, interleaved (re,im) store
    #pragma unroll
    for (int i = 0; i < 8; i++) {
        int row = mq*8 + i;
        int p = s_p[row];
        if (p < 0) continue;
        int ring = s_ring[row];
        const float* smr = g_mean_re + ring*FD;
        const float* smi = g_mean_im + ring*FD;
        float* op = out + (size_t)p * FD * 2;
        #pragma unroll
        for (int j = 0; j < 4; j++) {
            int n = nq*4 + j;
            float sr = smr[n], si = smi[n];
            float orr, oii;
            if (type == 0) { orr = 0.5f*(accr[i][j] + sr); oii = 0.5f*(acci[i][j] + si); }
            else           { orr = accr[i][j] - sr;        oii = acci[i][j] - si;        }
            *(float2*)&op[n*2] = make_float2(orr, oii);
        }
    }
}

// ---------------- launch ----------------
extern "C" void kernel_launch(void* const* d_in, const int* in_sizes, int n_in,
                              void* d_out, int out_size) {
    const float* img_re = (const float*)d_in[0];
    const float* img_im = (const float*)d_in[1];
    const int*   mask   = (const int*)  d_in[2];
    const float* w1re   = (const float*)d_in[5];
    const float* w1im   = (const float*)d_in[6];
    const float* w2re   = (const float*)d_in[7];
    const float* w2im   = (const float*)d_in[8];
    float* out = (float*)d_out;

    k_zero<<<(NR*FD + 255)/256, 256>>>();

    int accum_threads = NPIX * 32;
    k_accum<<<(accum_threads + 255)/256, 256>>>(img_re, img_im, mask);

    k_ringmm<<<NR, FD>>>(w1re, w1im);

    size_t smem = (size_t)(2*BM*132 + 2*FD*FD) * sizeof(float) + 2*BM*sizeof(int);
    cudaFuncSetAttribute(k_gemm, cudaFuncAttributeMaxDynamicSharedMemorySize, (int)smem);
    k_gemm<<<2*TILES_PER_TYPE, GEMM_THREADS, smem>>>(img_re, img_im,
                                                     w1re, w1im, w2re, w2im, out);
}

// round 3
// speedup vs baseline: 1.7631x; 1.7631x over previous
#include <cuda_runtime.h>
#include <cuda_bf16.h>
#include <math.h>
#include <stdint.h>

#define HH    512
#define NPIX  (HH*HH)
#define FD    128
#define NR    363
#define BM    64
#define GEMM_THREADS 256
#define GEMM_GRID 304

// smem layout
#define OFF_P    0
#define OFF_RING 256
#define OFF_A    512
#define SEGA     16384                        // one 64row x 128k bf16 seg
#define OFF_B    (OFF_A + 6*SEGA)             // 98816
#define MATB     32768                        // one 128n x 128k bf16 mat
#define SMEM_TOTAL (OFF_B + 4*MATB)           // 229888

// ---------------- device scratch ----------------
__device__ float g_sum_re[NR*FD];
__device__ float g_sum_im[NR*FD];
__device__ float g_mean_re[NR*FD];
__device__ float g_mean_im[NR*FD];
__device__ int   g_rcount[NR];
__device__ int   g_cnt[2];
__device__ int   g_list[2][NPIX];
// transposed bf16 hi/lo weights: [mat][n*128+k], mat: 0=w1re 1=w1im 2=w2re 3=w2im
__device__ __align__(16) __nv_bfloat16 g_Wh[4][FD*FD];
__device__ __align__(16) __nv_bfloat16 g_Wl[4][FD*FD];

// ---------------- helpers ----------------
__device__ __forceinline__ int ring_of(int p) {
    int i = (p >> 9) - 256;
    int j = (p & 511) - 256;
    int q = i*i + j*j;
    int s = __float2int_rd(sqrtf((float)q));
    while (s*s > q) --s;
    while ((s+1)*(s+1) <= q) ++s;
    return s;
}

__device__ __forceinline__ uint32_t smem_u32(const void* p) {
    uint32_t a;
    asm("{ .reg .u64 t; cvta.to.shared.u64 t, %1; cvt.u32.u64 %0, t; }" : "=r"(a) : "l"(p));
    return a;
}

// 16B-unit XOR swizzle within 256B rows (16 units): low-3-bit perm by row
__device__ __forceinline__ int phys_unit(int u, int row) {
    return (u & 8) | ((u & 7) ^ (row & 7));
}

#define LDSM_X4(r, addr) \
    asm volatile("ldmatrix.sync.aligned.m8n8.x4.shared.b16 {%0,%1,%2,%3}, [%4];" \
        : "=r"((r)[0]), "=r"((r)[1]), "=r"((r)[2]), "=r"((r)[3]) : "r"(addr))

__device__ __forceinline__ void mma4(float* d, const uint32_t* a, uint32_t b0, uint32_t b1) {
    asm volatile("mma.sync.aligned.m16n8k16.row.col.f32.bf16.bf16.f32 "
        "{%0,%1,%2,%3}, {%4,%5,%6,%7}, {%8,%9}, {%0,%1,%2,%3};"
        : "+f"(d[0]), "+f"(d[1]), "+f"(d[2]), "+f"(d[3])
        : "r"(a[0]), "r"(a[1]), "r"(a[2]), "r"(a[3]), "r"(b0), "r"(b1));
}

// one (A-seg, B-mat) pair -> 8 mma into one acc set (2 m-tiles x 4 n8-tiles)
__device__ __forceinline__ void do_pair(float (&acc)[2][4][4],
                                        uint32_t (&a)[2][4],
                                        uint32_t (&bq)[2][4]) {
    #pragma unroll
    for (int mt = 0; mt < 2; mt++) {
        #pragma unroll
        for (int n2 = 0; n2 < 2; n2++) {
            mma4(acc[mt][n2*2 + 0], a[mt], bq[n2][0], bq[n2][1]);
            mma4(acc[mt][n2*2 + 1], a[mt], bq[n2][2], bq[n2][3]);
        }
    }
}

// ---------------- kernel 0: zero ----------------
__global__ void k_zero() {
    int t = blockIdx.x * blockDim.x + threadIdx.x;
    if (t < NR*FD) { g_sum_re[t] = 0.f; g_sum_im[t] = 0.f; }
    if (t < NR)    g_rcount[t] = 0;
    if (t < 2)     g_cnt[t] = 0;
}

// ---------------- kernel 0b: transposed hi/lo bf16 weights ----------------
__global__ void k_prepW(const float* __restrict__ w1re, const float* __restrict__ w1im,
                        const float* __restrict__ w2re, const float* __restrict__ w2im) {
    int idx = blockIdx.x * blockDim.x + threadIdx.x;
    if (idx >= 4*FD*FD) return;
    int mat = idx >> 14;
    int rem = idx & (FD*FD - 1);
    int n = rem >> 7, k = rem & 127;
    const float* W = (mat == 0) ? w1re : (mat == 1) ? w1im : (mat == 2) ? w2re : w2im;
    float v = W[k*FD + n];
    __nv_bfloat16 hi = __float2bfloat16(v);
    __nv_bfloat16 lo = __float2bfloat16(v - __bfloat162float(hi));
    g_Wh[mat][n*FD + k] = hi;
    g_Wl[mat][n*FD + k] = lo;
}

// ---------------- kernel 1: ring reduce + partition ----------------
__global__ void k_accum(const float* __restrict__ img_re,
                        const float* __restrict__ img_im,
                        const int*   __restrict__ mask) {
    int gw   = (blockIdx.x * blockDim.x + threadIdx.x) >> 5;
    int lane = threadIdx.x & 31;
    if (gw >= NPIX) return;
    int p    = gw;
    int ring = ring_of(p);
    int m    = mask[p];
    if (lane == 0) {
        atomicAdd(&g_rcount[ring], 1);
        int pos = atomicAdd(&g_cnt[m], 1);
        g_list[m][pos] = p;
    }
    if (m == 0) {
        float4 a = ((const float4*)(img_re + (size_t)p * FD))[lane];
        float4 b = ((const float4*)(img_im + (size_t)p * FD))[lane];
        float* dr = &g_sum_re[ring*FD + lane*4];
        float* di = &g_sum_im[ring*FD + lane*4];
        asm volatile("red.global.add.v4.f32 [%0], {%1,%2,%3,%4};"
                     :: "l"(dr), "f"(a.x), "f"(a.y), "f"(a.z), "f"(a.w) : "memory");
        asm volatile("red.global.add.v4.f32 [%0], {%1,%2,%3,%4};"
                     :: "l"(di), "f"(b.x), "f"(b.y), "f"(b.z), "f"(b.w) : "memory");
    }
}

// ---------------- kernel 2: ring means (fp32) ----------------
__global__ void k_ringmm(const float* __restrict__ w1re,
                         const float* __restrict__ w1im) {
    __shared__ float sre[FD], sim[FD];
    int r = blockIdx.x, f = threadIdx.x;
    sre[f] = g_sum_re[r*FD + f];
    sim[f] = g_sum_im[r*FD + f];
    __syncthreads();
    float accr = 0.f, acci = 0.f;
    #pragma unroll 4
    for (int k = 0; k < FD; k++) {
        float wr = w1re[k*FD + f];
        float wi = w1im[k*FD + f];
        accr += sre[k]*wr - sim[k]*wi;
        acci += sre[k]*wi + sim[k]*wr;
    }
    float c = (float)max(g_rcount[r], 1);
    g_mean_re[r*FD + f] = accr / c;
    g_mean_im[r*FD + f] = acci / c;
}

// ---------------- kernel 3: HMMA split-bf16 gather GEMM + fused epilogue ----------------
// A segs: 0=Xr_hi 1=Xr_lo 2=Xi_hi 3=Xi_lo 4=-Xi_hi 5=-Xi_lo  (64x128 bf16 each)
// B mats: 0=Wr_hi 1=Wr_lo 2=Wi_hi 3=Wi_lo                    (128n x 128k bf16 each)
// re += Xrh@Wrh + Xrh@Wrl + Xrl@Wrh + (-Xih)@Wih + (-Xih)@Wil + (-Xil)@Wih
// im += Xrh@Wih + Xrh@Wil + Xrl@Wih +   Xih @Wrh +   Xih @Wrl +   Xil @Wrh
__global__ __launch_bounds__(GEMM_THREADS, 1)
void k_gemm(const float* __restrict__ img_re, const float* __restrict__ img_im,
            float* __restrict__ out) {
    extern __shared__ char sm[];
    const int t = threadIdx.x, lane = t & 31, wid = t >> 5;
    const int warp_m = wid >> 2;           // 0..1  (32 rows each)
    const int warp_n = wid & 3;            // 0..3  (32 cols each)

    const int half_grid = GEMM_GRID >> 1;
    const int type  = (blockIdx.x >= half_grid) ? 1 : 0;
    const int bid_t = type ? blockIdx.x - half_grid : blockIdx.x;
    const int cnt   = g_cnt[type];
    const int T     = (cnt + BM - 1) >> 6;

    uint32_t smb = smem_u32(sm);
    int* s_p    = (int*)(sm + OFF_P);
    int* s_ring = (int*)(sm + OFF_RING);

    // ---- stage all 4 B matrices once (swizzled) ----
    {
        const __nv_bfloat16* srcs[4] = { g_Wh[2*type], g_Wl[2*type],
                                         g_Wh[2*type+1], g_Wl[2*type+1] };
        #pragma unroll 4
        for (int i = t; i < 4*2048; i += GEMM_THREADS) {
            int mat = i >> 11, g = i & 2047;
            int n = g >> 4, u = g & 15;
            uint4 v = ((const uint4*)srcs[mat])[g];
            *(uint4*)(sm + OFF_B + mat*MATB + n*256 + phys_unit(u, n)*16) = v;
        }
    }

    for (int tile = bid_t; tile < T; tile += half_grid) {
        __syncthreads();   // prev-tile epilogue & B stage done before A rewrite

        // ---- stage A (6 segs) ----
        {
            int row = t >> 2, tq = t & 3;
            int grow = tile*BM + row;
            int p = -1, rg = 0;
            if (grow < cnt) { p = g_list[type][grow]; rg = ring_of(p); }
            if (tq == 0) { s_p[row] = p; s_ring[row] = rg; }
            const float4* ar = (const float4*)(img_re + (size_t)(p < 0 ? 0 : p) * FD);
            const float4* ai = (const float4*)(img_im + (size_t)(p < 0 ? 0 : p) * FD);
            float4 z = make_float4(0.f, 0.f, 0.f, 0.f);
            #pragma unroll
            for (int i = 0; i < 8; i++) {
                int k4 = tq*8 + i;
                int u  = k4 >> 1;
                uint32_t base = (uint32_t)(row*256 + phys_unit(u, row)*16 + (k4 & 1)*8);
                // real
                float4 v = (p >= 0) ? ar[k4] : z;
                __nv_bfloat162 h01 = __floats2bfloat162_rn(v.x, v.y);
                __nv_bfloat162 h23 = __floats2bfloat162_rn(v.z, v.w);
                __nv_bfloat162 l01 = __floats2bfloat162_rn(v.x - __low2float(h01), v.y - __high2float(h01));
                __nv_bfloat162 l23 = __floats2bfloat162_rn(v.z - __low2float(h23), v.w - __high2float(h23));
                *(uint2*)(sm + OFF_A + 0*SEGA + base) = make_uint2(*(uint32_t*)&h01, *(uint32_t*)&h23);
                *(uint2*)(sm + OFF_A + 1*SEGA + base) = make_uint2(*(uint32_t*)&l01, *(uint32_t*)&l23);
                // imag (+ negated copies: bf16 sign-flip is exact)
                v = (p >= 0) ? ai[k4] : z;
                h01 = __floats2bfloat162_rn(v.x, v.y);
                h23 = __floats2bfloat162_rn(v.z, v.w);
                l01 = __floats2bfloat162_rn(v.x - __low2float(h01), v.y - __high2float(h01));
                l23 = __floats2bfloat162_rn(v.z - __low2float(h23), v.w - __high2float(h23));
                uint32_t uh01 = *(uint32_t*)&h01, uh23 = *(uint32_t*)&h23;
                uint32_t ul01 = *(uint32_t*)&l01, ul23 = *(uint32_t*)&l23;
                *(uint2*)(sm + OFF_A + 2*SEGA + base) = make_uint2(uh01, uh23);
                *(uint2*)(sm + OFF_A + 3*SEGA + base) = make_uint2(ul01, ul23);
                *(uint2*)(sm + OFF_A + 4*SEGA + base) = make_uint2(uh01 ^ 0x80008000u, uh23 ^ 0x80008000u);
                *(uint2*)(sm + OFF_A + 5*SEGA + base) = make_uint2(ul01 ^ 0x80008000u, ul23 ^ 0x80008000u);
            }
        }
        __syncthreads();

        // ---- compute ----
        float acc_re[2][4][4], acc_im[2][4][4];
        #pragma unroll
        for (int mt = 0; mt < 2; mt++)
            #pragma unroll
            for (int nt = 0; nt < 4; nt++)
                #pragma unroll
                for (int e = 0; e < 4; e++) { acc_re[mt][nt][e] = 0.f; acc_im[mt][nt][e] = 0.f; }

        for (int ks = 0; ks < 8; ks++) {
            uint32_t a[6][2][4];
            #pragma unroll
            for (int mt = 0; mt < 2; mt++) {
                int row = warp_m*32 + mt*16 + (lane & 15);
                int u   = 2*ks + (lane >> 4);
                uint32_t addr = smb + OFF_A + (uint32_t)(row*256 + phys_unit(u, row)*16);
                #pragma unroll
                for (int s = 0; s < 6; s++)
                    LDSM_X4(a[s][mt], addr + s*SEGA);
            }
            uint32_t bq[4][2][4];
            #pragma unroll
            for (int n2 = 0; n2 < 2; n2++) {
                int n = warp_n*32 + n2*16 + (lane & 7) + ((lane & 16) ? 8 : 0);
                int u = 2*ks + ((lane & 8) ? 1 : 0);
                uint32_t addr = smb + OFF_B + (uint32_t)(n*256 + phys_unit(u, n)*16);
                #pragma unroll
                for (int m = 0; m < 4; m++)
                    LDSM_X4(bq[m][n2], addr + m*MATB);
            }
            // re
            do_pair(acc_re, a[0], bq[0]);
            do_pair(acc_re, a[0], bq[1]);
            do_pair(acc_re, a[1], bq[0]);
            do_pair(acc_re, a[4], bq[2]);
            do_pair(acc_re, a[4], bq[3]);
            do_pair(acc_re, a[5], bq[2]);
            // im
            do_pair(acc_im, a[0], bq[2]);
            do_pair(acc_im, a[0], bq[3]);
            do_pair(acc_im, a[1], bq[2]);
            do_pair(acc_im, a[2], bq[0]);
            do_pair(acc_im, a[2], bq[1]);
            do_pair(acc_im, a[3], bq[0]);
        }

        // ---- fused epilogue ----
        #pragma unroll
        for (int mt = 0; mt < 2; mt++) {
            #pragma unroll
            for (int rv = 0; rv < 2; rv++) {
                int r = warp_m*32 + mt*16 + rv*8 + (lane >> 2);
                int p = s_p[r];
                if (p < 0) continue;
                int ring = s_ring[r];
                const float* mre = g_mean_re + ring*FD;
                const float* mim = g_mean_im + ring*FD;
                float* op = out + (size_t)p * 256;
                #pragma unroll
                for (int nt = 0; nt < 4; nt++) {
                    int c = warp_n*32 + nt*8 + (lane & 3)*2;
                    float re0 = acc_re[mt][nt][rv*2 + 0], re1 = acc_re[mt][nt][rv*2 + 1];
                    float im0 = acc_im[mt][nt][rv*2 + 0], im1 = acc_im[mt][nt][rv*2 + 1];
                    float2 mr = *(const float2*)&mre[c];
                    float2 mi = *(const float2*)&mim[c];
                    float4 o;
                    if (type == 0) {
                        o.x = 0.5f*(re0 + mr.x); o.y = 0.5f*(im0 + mi.x);
                        o.z = 0.5f*(re1 + mr.y); o.w = 0.5f*(im1 + mi.y);
                    } else {
                        o.x = re0 - mr.x; o.y = im0 - mi.x;
                        o.z = re1 - mr.y; o.w = im1 - mi.y;
                    }
                    *(float4*)&op[c*2] = o;
                }
            }
        }
    }
}

// ---------------- launch ----------------
extern "C" void kernel_launch(void* const* d_in, const int* in_sizes, int n_in,
                              void* d_out, int out_size) {
    const float* img_re = (const float*)d_in[0];
    const float* img_im = (const float*)d_in[1];
    const int*   mask   = (const int*)  d_in[2];
    const float* w1re   = (const float*)d_in[5];
    const float* w1im   = (const float*)d_in[6];
    const float* w2re   = (const float*)d_in[7];
    const float* w2im   = (const float*)d_in[8];
    float* out = (float*)d_out;

    k_zero<<<(NR*FD + 255)/256, 256>>>();
    k_prepW<<<(4*FD*FD + 255)/256, 256>>>(w1re, w1im, w2re, w2im);

    int accum_threads = NPIX * 32;
    k_accum<<<(accum_threads + 255)/256, 256>>>(img_re, img_im, mask);

    k_ringmm<<<NR, FD>>>(w1re, w1im);

    cudaFuncSetAttribute(k_gemm, cudaFuncAttributeMaxDynamicSharedMemorySize, SMEM_TOTAL);
    k_gemm<<<GEMM_GRID, GEMM_THREADS, SMEM_TOTAL>>>(img_re, img_im, out);
}

// round 4
// speedup vs baseline: 4.2133x; 2.3897x over previous
#include <cuda_runtime.h>
#include <cuda_fp16.h>
#include <math.h>
#include <stdint.h>

#define HH    512
#define NPIX  (HH*HH)
#define FD    128
#define NR    363
#define BM    64
#define GEMM_THREADS 256
#define GEMM_GRID 296      // 2 per SM
#define HALF_GRID (GEMM_GRID/2)

// k_gemm smem layout
#define OFF_P    0
#define OFF_RING 256
#define OFF_A    512
#define SEGA     16384                       // 64 rows x 256B fp16
#define OFF_B    (OFF_A + 2*SEGA)            // 33280
#define MATB     32768                       // 128n x 256B fp16
#define SMEM_TOTAL (OFF_B + 2*MATB)          // 98816 (~96.5KB) -> 2 CTAs/SM

// ---------------- device scratch ----------------
__device__ float g_sum_re[NR*FD];
__device__ float g_sum_im[NR*FD];
__device__ float g_mean_re[NR*FD];
__device__ float g_mean_im[NR*FD];
__device__ int   g_rcount[NR];     // all-pixel ring counts (denominator)
__device__ int   g_ucnt[NR];       // mask==0 ring counts
__device__ int   g_base[NR+1];     // ring bases into list_u
__device__ int   g_cur[NR+1];      // scatter cursors ([NR] = cor list cursor)
__device__ int   g_cnt[2];         // [0]=uncor total, [1]=cor total
__device__ int   g_list[2][NPIX];  // [0]=uncor (ring-grouped), [1]=cor
// transposed fp16 weights [mat][n*128+k], mat: 0=w1re 1=w1im 2=w2re 3=w2im
__device__ __align__(16) __half g_Wf[4][FD*FD];

// ---------------- helpers ----------------
__device__ __forceinline__ int ring_of(int p) {
    int i = (p >> 9) - 256;
    int j = (p & 511) - 256;
    int q = i*i + j*j;
    int s = __float2int_rd(sqrtf((float)q));
    while (s*s > q) --s;
    while ((s+1)*(s+1) <= q) ++s;
    return s;
}

__device__ __forceinline__ uint32_t smem_u32(const void* p) {
    uint32_t a;
    asm("{ .reg .u64 t; cvta.to.shared.u64 t, %1; cvt.u32.u64 %0, t; }" : "=r"(a) : "l"(p));
    return a;
}

// 16B-unit XOR swizzle within 256B rows (16 units): low-3-bit perm by row
__device__ __forceinline__ int phys_unit(int u, int row) {
    return (u & 8) | ((u & 7) ^ (row & 7));
}

#define LDSM_X4(r, addr) \
    asm volatile("ldmatrix.sync.aligned.m8n8.x4.shared.b16 {%0,%1,%2,%3}, [%4];" \
        : "=r"((r)[0]), "=r"((r)[1]), "=r"((r)[2]), "=r"((r)[3]) : "r"(addr))

__device__ __forceinline__ void mma4(float* d, const uint32_t* a, uint32_t b0, uint32_t b1) {
    asm volatile("mma.sync.aligned.m16n8k16.row.col.f32.f16.f16.f32 "
        "{%0,%1,%2,%3}, {%4,%5,%6,%7}, {%8,%9}, {%0,%1,%2,%3};"
        : "+f"(d[0]), "+f"(d[1]), "+f"(d[2]), "+f"(d[3])
        : "r"(a[0]), "r"(a[1]), "r"(a[2]), "r"(a[3]), "r"(b0), "r"(b1));
}

// one (A-seg, B-mat) pair -> 8 mma into one acc set (2 m-tiles x 4 n8-tiles)
__device__ __forceinline__ void do_pair(float (&acc)[2][4][4],
                                        uint32_t (&a)[2][4],
                                        uint32_t (&bq)[2][4]) {
    #pragma unroll
    for (int mt = 0; mt < 2; mt++) {
        #pragma unroll
        for (int n2 = 0; n2 < 2; n2++) {
            mma4(acc[mt][n2*2 + 0], a[mt], bq[n2][0], bq[n2][1]);
            mma4(acc[mt][n2*2 + 1], a[mt], bq[n2][2], bq[n2][3]);
        }
    }
}

// ---------------- kernel: zero counters ----------------
__global__ void k_zero() {
    int t = blockIdx.x * blockDim.x + threadIdx.x;
    if (t < NR) { g_rcount[t] = 0; g_ucnt[t] = 0; }
}

// ---------------- kernel: transposed fp16 weights ----------------
__global__ void k_prepW(const float* __restrict__ w1re, const float* __restrict__ w1im,
                        const float* __restrict__ w2re, const float* __restrict__ w2im) {
    int idx = blockIdx.x * blockDim.x + threadIdx.x;
    if (idx >= 4*FD*FD) return;
    int mat = idx >> 14;
    int rem = idx & (FD*FD - 1);
    int n = rem >> 7, k = rem & 127;
    const float* W = (mat == 0) ? w1re : (mat == 1) ? w1im : (mat == 2) ? w2re : w2im;
    g_Wf[mat][n*FD + k] = __float2half_rn(W[k*FD + n]);
}

// ---------------- kernel: histogram (block-aggregated) ----------------
// 256 blocks x 256 threads x 4 pixels
__global__ void k_count(const int* __restrict__ mask) {
    __shared__ int scnt[2*NR];
    int t = threadIdx.x;
    for (int i = t; i < 2*NR; i += 256) scnt[i] = 0;
    __syncthreads();
    int base = blockIdx.x * 1024;
    #pragma unroll
    for (int i = 0; i < 4; i++) {
        int p = base + i*256 + t;
        int r = ring_of(p);
        int m = mask[p];
        atomicAdd(&scnt[r], 1);
        if (m == 0) atomicAdd(&scnt[NR + r], 1);
    }
    __syncthreads();
    for (int i = t; i < NR; i += 256) {
        int c = scnt[i];       if (c) atomicAdd(&g_rcount[i], c);
        int u = scnt[NR + i];  if (u) atomicAdd(&g_ucnt[i], u);
    }
}

// ---------------- kernel: serial scan ----------------
__global__ void k_scan() {
    int s = 0;
    for (int r = 0; r < NR; r++) {
        g_base[r] = s; g_cur[r] = s;
        s += g_ucnt[r];
    }
    g_base[NR] = s;
    g_cur[NR] = 0;
    g_cnt[0] = s;
    g_cnt[1] = NPIX - s;
}

// ---------------- kernel: scatter into ring-grouped lists ----------------
__global__ void k_scatter(const int* __restrict__ mask) {
    __shared__ int lcnt[NR+1];
    __shared__ int sbase[NR+1];
    int t = threadIdx.x;
    for (int i = t; i < NR+1; i += 256) lcnt[i] = 0;
    __syncthreads();
    int base = blockIdx.x * 1024;
    int key[4], lpos[4];
    #pragma unroll
    for (int i = 0; i < 4; i++) {
        int p = base + i*256 + t;
        int m = mask[p];
        key[i] = m ? NR : ring_of(p);
        lpos[i] = atomicAdd(&lcnt[key[i]], 1);
    }
    __syncthreads();
    for (int i = t; i < NR+1; i += 256) {
        int c = lcnt[i];
        if (c) sbase[i] = atomicAdd(&g_cur[i], c);
    }
    __syncthreads();
    #pragma unroll
    for (int i = 0; i < 4; i++) {
        int p = base + i*256 + t;
        int pos = sbase[key[i]] + lpos[i];
        if (key[i] == NR) g_list[1][pos] = p;
        else              g_list[0][pos] = p;
    }
}

// ---------------- kernel: atomic-free ring sums ----------------
// grid (NR, 8): ring r, feature group g (16 feats). block 128.
__global__ void k_ringsum(const float* __restrict__ img_re,
                          const float* __restrict__ img_im) {
    __shared__ float sred[4][32];
    int r = blockIdx.x, g = blockIdx.y;
    int t = threadIdx.x, lane = t & 31, wid = t >> 5;
    int b0 = g_base[r], n = g_base[r+1] - b0;
    const int* lst = g_list[0] + b0;
    float ar[16], ai[16];
    #pragma unroll
    for (int f = 0; f < 16; f++) { ar[f] = 0.f; ai[f] = 0.f; }
    for (int i = t; i < n; i += 128) {
        int p = lst[i];
        const float4* pr = (const float4*)(img_re + (size_t)p*FD + g*16);
        const float4* pi = (const float4*)(img_im + (size_t)p*FD + g*16);
        #pragma unroll
        for (int c = 0; c < 4; c++) {
            float4 v = pr[c];
            ar[c*4+0] += v.x; ar[c*4+1] += v.y; ar[c*4+2] += v.z; ar[c*4+3] += v.w;
            v = pi[c];
            ai[c*4+0] += v.x; ai[c*4+1] += v.y; ai[c*4+2] += v.z; ai[c*4+3] += v.w;
        }
    }
    // warp reduce all 32 accumulators
    #pragma unroll
    for (int f = 0; f < 16; f++) {
        #pragma unroll
        for (int m = 16; m > 0; m >>= 1) {
            ar[f] += __shfl_xor_sync(0xFFFFFFFF, ar[f], m);
            ai[f] += __shfl_xor_sync(0xFFFFFFFF, ai[f], m);
        }
    }
    if (lane == 0) {
        #pragma unroll
        for (int f = 0; f < 16; f++) {
            sred[wid][f]      = ar[f];
            sred[wid][16 + f] = ai[f];
        }
    }
    __syncthreads();
    if (t < 32) {
        float s = sred[0][t] + sred[1][t] + sred[2][t] + sred[3][t];
        int f = t & 15;
        if (t < 16) g_sum_re[r*FD + g*16 + f] = s;
        else        g_sum_im[r*FD + g*16 + f] = s;
    }
}

// ---------------- kernel: ring means (fp32) ----------------
__global__ void k_ringmm(const float* __restrict__ w1re,
                         const float* __restrict__ w1im) {
    __shared__ float sre[FD], sim[FD];
    int r = blockIdx.x, f = threadIdx.x;
    sre[f] = g_sum_re[r*FD + f];
    sim[f] = g_sum_im[r*FD + f];
    __syncthreads();
    float accr = 0.f, acci = 0.f;
    #pragma unroll 8
    for (int k = 0; k < FD; k++) {
        float wr = w1re[k*FD + f];
        float wi = w1im[k*FD + f];
        accr += sre[k]*wr - sim[k]*wi;
        acci += sre[k]*wi + sim[k]*wr;
    }
    float c = (float)max(g_rcount[r], 1);
    g_mean_re[r*FD + f] = accr / c;
    g_mean_im[r*FD + f] = acci / c;
}

// ---------------- kernel: fp16 HMMA gather GEMM + fused epilogue ----------------
// A segs: 0=Xr 1=Xi (64x128 fp16). -Xi derived by register XOR.
// B mats: 0=Wr 1=Wi (128n x 128k fp16).
// accR = Xr@Wr + (-Xi)@Wi ; accI = Xr@Wi + Xi@Wr
__global__ __launch_bounds__(GEMM_THREADS, 2)
void k_gemm(const float* __restrict__ img_re, const float* __restrict__ img_im,
            float* __restrict__ out) {
    extern __shared__ char sm[];
    const int t = threadIdx.x, lane = t & 31, wid = t >> 5;
    const int warp_m = wid >> 2;           // 0..1  (32 rows each)
    const int warp_n = wid & 3;            // 0..3  (32 cols each)

    const int type  = (blockIdx.x >= HALF_GRID) ? 1 : 0;
    const int bid_t = type ? blockIdx.x - HALF_GRID : blockIdx.x;
    const int cnt   = g_cnt[type];
    const int T     = (cnt + BM - 1) >> 6;

    uint32_t smb = smem_u32(sm);
    int* s_p    = (int*)(sm + OFF_P);
    int* s_ring = (int*)(sm + OFF_RING);

    // ---- stage B: Wr, Wi fp16 transposed, swizzled ----
    {
        const __half* srcs[2] = { g_Wf[2*type], g_Wf[2*type+1] };
        #pragma unroll 4
        for (int i = t; i < 2*2048; i += GEMM_THREADS) {
            int mat = i >> 11, g = i & 2047;
            int n = g >> 4, u = g & 15;
            uint4 v = ((const uint4*)srcs[mat])[g];
            *(uint4*)(sm + OFF_B + mat*MATB + n*256 + phys_unit(u, n)*16) = v;
        }
    }

    for (int tile = bid_t; tile < T; tile += HALF_GRID) {
        __syncthreads();   // prev epilogue / B-stage done before A rewrite

        // ---- stage A (fp16 Xr, Xi) ----
        {
            int row = t >> 2, tq = t & 3;
            int grow = tile*BM + row;
            int p = -1, rg = 0;
            if (grow < cnt) { p = g_list[type][grow]; rg = ring_of(p); }
            if (tq == 0) { s_p[row] = p; s_ring[row] = rg; }
            const float4* ar = (const float4*)(img_re + (size_t)(p < 0 ? 0 : p) * FD);
            const float4* ai = (const float4*)(img_im + (size_t)(p < 0 ? 0 : p) * FD);
            float4 z = make_float4(0.f, 0.f, 0.f, 0.f);
            #pragma unroll
            for (int i = 0; i < 8; i++) {
                int k4 = tq*8 + i;
                int u  = k4 >> 1;
                uint32_t base = (uint32_t)(row*256 + phys_unit(u, row)*16 + (k4 & 1)*8);
                float4 v = (p >= 0) ? ar[k4] : z;
                __half2 h01 = __floats2half2_rn(v.x, v.y);
                __half2 h23 = __floats2half2_rn(v.z, v.w);
                *(uint2*)(sm + OFF_A + base) = make_uint2(*(uint32_t*)&h01, *(uint32_t*)&h23);
                v = (p >= 0) ? ai[k4] : z;
                h01 = __floats2half2_rn(v.x, v.y);
                h23 = __floats2half2_rn(v.z, v.w);
                *(uint2*)(sm + OFF_A + SEGA + base) = make_uint2(*(uint32_t*)&h01, *(uint32_t*)&h23);
            }
        }
        __syncthreads();

        // ---- compute ----
        float accR[2][4][4], accI[2][4][4];
        #pragma unroll
        for (int mt = 0; mt < 2; mt++)
            #pragma unroll
            for (int nt = 0; nt < 4; nt++)
                #pragma unroll
                for (int e = 0; e < 4; e++) { accR[mt][nt][e] = 0.f; accI[mt][nt][e] = 0.f; }

        #pragma unroll
        for (int ks = 0; ks < 8; ks++) {
            uint32_t a[2][2][4];     // [seg][mt][4]
            #pragma unroll
            for (int mt = 0; mt < 2; mt++) {
                int row = warp_m*32 + mt*16 + (lane & 15);
                int u   = 2*ks + (lane >> 4);
                uint32_t addr = smb + OFF_A + (uint32_t)(row*256 + phys_unit(u, row)*16);
                LDSM_X4(a[0][mt], addr);
                LDSM_X4(a[1][mt], addr + SEGA);
            }
            uint32_t b[2][2][4];     // [mat][n2][4]
            #pragma unroll
            for (int n2 = 0; n2 < 2; n2++) {
                int n = warp_n*32 + n2*16 + (lane & 7) + ((lane & 16) ? 8 : 0);
                int u = 2*ks + ((lane & 8) ? 1 : 0);
                uint32_t addr = smb + OFF_B + (uint32_t)(n*256 + phys_unit(u, n)*16);
                LDSM_X4(b[0][n2], addr);
                LDSM_X4(b[1][n2], addr + MATB);
            }
            uint32_t an[2][4];       // -Xi via sign flip (exact)
            #pragma unroll
            for (int mt = 0; mt < 2; mt++)
                #pragma unroll
                for (int e = 0; e < 4; e++) an[mt][e] = a[1][mt][e] ^ 0x80008000u;

            do_pair(accR, a[0], b[0]);   // Xr@Wr
            do_pair(accR, an,   b[1]);   // -Xi@Wi
            do_pair(accI, a[0], b[1]);   // Xr@Wi
            do_pair(accI, a[1], b[0]);   // Xi@Wr
        }

        // ---- fused epilogue ----
        #pragma unroll
        for (int mt = 0; mt < 2; mt++) {
            #pragma unroll
            for (int rv = 0; rv < 2; rv++) {
                int r = warp_m*32 + mt*16 + rv*8 + (lane >> 2);
                int p = s_p[r];
                if (p < 0) continue;
                int ring = s_ring[r];
                const float* mre = g_mean_re + ring*FD;
                const float* mim = g_mean_im + ring*FD;
                float* op = out + (size_t)p * 256;
                #pragma unroll
                for (int nt = 0; nt < 4; nt++) {
                    int c = warp_n*32 + nt*8 + (lane & 3)*2;
                    float re0 = accR[mt][nt][rv*2 + 0], re1 = accR[mt][nt][rv*2 + 1];
                    float im0 = accI[mt][nt][rv*2 + 0], im1 = accI[mt][nt][rv*2 + 1];
                    float2 mr = *(const float2*)&mre[c];
                    float2 mi = *(const float2*)&mim[c];
                    float4 o;
                    if (type == 0) {
                        o.x = 0.5f*(re0 + mr.x); o.y = 0.5f*(im0 + mi.x);
                        o.z = 0.5f*(re1 + mr.y); o.w = 0.5f*(im1 + mi.y);
                    } else {
                        o.x = re0 - mr.x; o.y = im0 - mi.x;
                        o.z = re1 - mr.y; o.w = im1 - mi.y;
                    }
                    *(float4*)&op[c*2] = o;
                }
            }
        }
    }
}

// ---------------- launch ----------------
extern "C" void kernel_launch(void* const* d_in, const int* in_sizes, int n_in,
                              void* d_out, int out_size) {
    const float* img_re = (const float*)d_in[0];
    const float* img_im = (const float*)d_in[1];
    const int*   mask   = (const int*)  d_in[2];
    const float* w1re   = (const float*)d_in[5];
    const float* w1im   = (const float*)d_in[6];
    const float* w2re   = (const float*)d_in[7];
    const float* w2im   = (const float*)d_in[8];
    float* out = (float*)d_out;

    k_zero<<<1, 512>>>();
    k_prepW<<<(4*FD*FD + 255)/256, 256>>>(w1re, w1im, w2re, w2im);
    k_count<<<NPIX/1024, 256>>>(mask);
    k_scan<<<1, 1>>>();
    k_scatter<<<NPIX/1024, 256>>>(mask);
    k_ringsum<<<dim3(NR, 8), 128>>>(img_re, img_im);
    k_ringmm<<<NR, FD>>>(w1re, w1im);

    cudaFuncSetAttribute(k_gemm, cudaFuncAttributeMaxDynamicSharedMemorySize, SMEM_TOTAL);
    k_gemm<<<GEMM_GRID, GEMM_THREADS, SMEM_TOTAL>>>(img_re, img_im, out);
}